// round 9
// baseline (speedup 1.0000x reference)
#include <cuda_runtime.h>
#include <cstdint>
#include <math.h>
#include <math_constants.h>

#define DIMS 32
#define NCAP 500000
#define TPB  512
#define MSLOTS 1024
#define PERMAX 4096   // max points per block (supports nb >= 123)

// ---- static device scratch (no allocations allowed) ----
// blocked layout: [bid][k][j_local], region stride DIMS*per float2 per block
__device__ float2 g_xs[(size_t)DIMS * (NCAP + 8192)];
__device__ unsigned long long g_amin[MSLOTS];          // per-step argmin key (atomicMin)
__device__ unsigned g_cnt[MSLOTS];                     // per-step barrier counters
__device__ float  g_ell2v;

// float -> order-preserving uint32
__device__ __forceinline__ unsigned f2ord(float f) {
    unsigned b = __float_as_uint(f);
    return (b & 0x80000000u) ? ~b : (b | 0x80000000u);
}

__global__ void k_setup(const unsigned* s0, const unsigned* s1) {
    for (int i = 0; i < MSLOTS; i++) { g_amin[i] = 0xFFFFFFFFFFFFFFFFull; g_cnt[i] = 0u; }
    float ell = 1.0f;
    unsigned u0 = s0 ? s0[0] : 0u;
    unsigned u1 = s1 ? s1[0] : 0u;
    unsigned e0 = (u0 >> 23) & 0xffu;
    unsigned e1 = (u1 >> 23) & 0xffu;
    if (e0 >= 64u && e0 <= 191u)      ell = __uint_as_float(u0);
    else if (e1 >= 64u && e1 <= 191u) ell = __uint_as_float(u1);
    float e2 = __fmul_rn(ell, ell);
    if (!(e2 > 1e-20f) || !(e2 < 1e20f)) e2 = 1.0f;
    g_ell2v = e2;
}

// Transpose x,s (row-major [N][32]) into per-block contiguous [bid][k][jl] float2.
__global__ void __launch_bounds__(256) k_transpose(const float4* __restrict__ x4,
                                                   const float4* __restrict__ s4,
                                                   int n, int per) {
    int j = blockIdx.x * blockDim.x + threadIdx.x;
    if (j >= n) return;
    int b  = j / per;
    int jl = j - b * per;
    float2* dst = g_xs + (size_t)b * DIMS * per + jl;
#pragma unroll
    for (int i = 0; i < DIMS / 4; i++) {
        float4 xv = x4[(size_t)j * (DIMS / 4) + i];
        float4 sv = s4[(size_t)j * (DIMS / 4) + i];
        dst[(size_t)(4 * i + 0) * per] = make_float2(xv.x, sv.x);
        dst[(size_t)(4 * i + 1) * per] = make_float2(xv.y, sv.y);
        dst[(size_t)(4 * i + 2) * per] = make_float2(xv.z, sv.z);
        dst[(size_t)(4 * i + 3) * per] = make_float2(xv.w, sv.w);
    }
}

__device__ __forceinline__ void argmin2(float& v, int& i, float v2, int i2) {
    if (v2 < v || (v2 == v && i2 < i)) { v = v2; i = i2; }
}

template <int NT>
__device__ __forceinline__ void block_argmin(float& v, int& i, float* rv, int* ri, int tid) {
#pragma unroll
    for (int off = 16; off > 0; off >>= 1) {
        float v2 = __shfl_down_sync(0xffffffffu, v, off);
        int   i2 = __shfl_down_sync(0xffffffffu, i, off);
        argmin2(v, i, v2, i2);
    }
    if ((tid & 31) == 0) { rv[tid >> 5] = v; ri[tid >> 5] = i; }
    __syncthreads();
    if (tid < 32) {
        const int nw = NT >> 5;
        float vv = (tid < nw) ? rv[tid] : CUDART_INF_F;
        int   ii = (tid < nw) ? ri[tid] : 0x7fffffff;
#pragma unroll
        for (int off = 16; off > 0; off >>= 1) {
            float v2 = __shfl_down_sync(0xffffffffu, vv, off);
            int   i2 = __shfl_down_sync(0xffffffffu, ii, off);
            argmin2(vv, ii, v2, i2);
        }
        if (tid == 0) { rv[0] = vv; ri[0] = ii; }
    }
    __syncthreads();
    v = rv[0]; i = ri[0];
}

// XLA row-reduce tree over 32 elements: pair offsets 16,8,4,2,1
__device__ __forceinline__ float tree16(float* p) {
#pragma unroll
    for (int k = 0; k < 8; k++) p[k] = __fadd_rn(p[k], p[k + 8]);
#pragma unroll
    for (int k = 0; k < 4; k++) p[k] = __fadd_rn(p[k], p[k + 4]);
    p[0] = __fadd_rn(p[0], p[2]); p[1] = __fadd_rn(p[1], p[3]);
    return __fadd_rn(p[0], p[1]);
}

// Per-step cross-SM exchange: atomicMin + counter-barrier (pure L2 atomics).
__device__ __forceinline__ int step_exchange(int t, float bv, int bi, int tid, int nb) {
    __shared__ unsigned long long key_sh;
    if (tid == 0) {
        unsigned long long key = ((unsigned long long)f2ord(bv) << 32) | (unsigned)bi;
        atomicMin(&g_amin[t], key);
        __threadfence();
        atomicAdd(&g_cnt[t], 1u);
        long spins = 0;
        while (atomicAdd(&g_cnt[t], 0u) < (unsigned)nb) {
            __nanosleep(64);
            if (++spins > 2000000L) break;
        }
        key_sh = atomicAdd(&g_amin[t], 0ull);
    }
    __syncthreads();
    return (int)(unsigned)(key_sh & 0xffffffffull);
}

// ---- persistent kernel: whole greedy loop; obj/wlp resident in SMEM ----
__global__ void __launch_bounds__(TPB) k_stein_pers(
    const float* __restrict__ x, const float* __restrict__ logp,
    const float* __restrict__ sp, const float* __restrict__ lap,
    float* __restrict__ out, int nb, int n, int m, int per) {
    const int tid = threadIdx.x;
    const int bid = blockIdx.x;
    float ell2 = g_ell2v;
    if (!(ell2 > 1e-20f) || !(ell2 < 1e20f)) ell2 = 1.0f;
    const float e4 = __fmul_rn(ell2, ell2);
    const float w = __fdiv_rn(1.0f, (float)m);
    const float dterm = __fdiv_rn((float)DIMS, ell2);

    __shared__ float obj_sh[PERMAX];
    __shared__ float wlp_sh[PERMAX];
    __shared__ float piv[2 * DIMS];
    __shared__ float rv_sh[TPB / 32];
    __shared__ int   ri_sh[TPB / 32];

    const int j0  = bid * per;
    const int cnt = min(n - j0, per);           // points owned by this block
    const float2* blk = g_xs + (size_t)bid * DIMS * per;

    // ---- step 0: obj0 = (d/ell2 + tree_sum(s*s)) + laplace - w*log_p ----
    {
        float bv = CUDART_INF_F; int bi = 0x7fffffff;
        const float4* s4 = (const float4*)sp;
        for (int jl = tid; jl < cnt; jl += TPB) {
            int j = j0 + jl;
            float sv[DIMS];
            const float4* row = s4 + (size_t)j * (DIMS / 4);
#pragma unroll
            for (int i = 0; i < DIMS / 4; i++) {
                float4 v = row[i];
                sv[4 * i] = v.x; sv[4 * i + 1] = v.y; sv[4 * i + 2] = v.z; sv[4 * i + 3] = v.w;
            }
            float p[16];
#pragma unroll
            for (int k = 0; k < 16; k++)
                p[k] = __fadd_rn(__fmul_rn(sv[k], sv[k]), __fmul_rn(sv[k + 16], sv[k + 16]));
            float s2 = tree16(p);
            float wl = __fmul_rn(w, logp[j]);
            wlp_sh[jl] = wl;
            float o = __fsub_rn(__fadd_rn(__fadd_rn(dterm, s2), lap[j]), wl);
            obj_sh[jl] = o;
            argmin2(bv, bi, o, j);
        }
        block_argmin<TPB>(bv, bi, rv_sh, ri_sh, tid);
        int idx = step_exchange(0, bv, bi, tid, nb);
        if (bid == 0 && tid == 0) out[0] = (float)idx;   // output dtype: float32
        if (tid < 2 * DIMS)
            piv[tid] = (tid < DIMS) ? x[(size_t)idx * DIMS + tid]
                                    : sp[(size_t)idx * DIMS + (tid - DIMS)];
        __syncthreads();
    }

    // ---- steps 1..m-1 ----
    for (int t = 1; t < m; t++) {
        float bv = CUDART_INF_F; int bi = 0x7fffffff;
        for (int jl = tid; jl < cnt; jl += TPB) {
            float r2p[16], ap[16], bp[16], cp[16];
            const float2* p0 = blk + jl;
#pragma unroll
            for (int k = 0; k < 16; k++) {
                float2 v0 = __ldcs(&p0[(size_t)k * per]);
                float2 v1 = __ldcs(&p0[(size_t)(k + 16) * per]);
                float xk0 = piv[k],      sk0 = piv[DIMS + k];
                float xk1 = piv[k + 16], sk1 = piv[DIMS + k + 16];
                float d0 = __fsub_rn(xk0, v0.x);
                float d1 = __fsub_rn(xk1, v1.x);
                r2p[k] = __fadd_rn(__fmul_rn(d0, d0),   __fmul_rn(d1, d1));
                ap[k]  = __fadd_rn(__fmul_rn(d0, sk0),  __fmul_rn(d1, sk1));
                bp[k]  = __fadd_rn(__fmul_rn(v0.y, d0), __fmul_rn(v1.y, d1));
                cp[k]  = __fadd_rn(__fmul_rn(v0.y, sk0),__fmul_rn(v1.y, sk1));
            }
            float r2   = tree16(r2p);
            float a    = tree16(ap);
            float b    = tree16(bp);
            float sdot = tree16(cp);

            float q    = __fadd_rn(1.0f, __fdiv_rn(r2, ell2));
            float g    = powf(q, -1.5f);
            float p25  = powf(q, -2.5f);
            float rq   = rsqrtf(q);
            float cross = __fdiv_rn(__fsub_rn(a, b), ell2);
            float t1 = __fmul_rn(dterm, g);
            float t2 = __fmul_rn(__fdiv_rn(__fmul_rn(3.0f, r2), e4), p25);
            float t3 = __fmul_rn(cross, g);
            float t4 = __fmul_rn(sdot, rq);
            float ki = __fadd_rn(__fadd_rn(__fsub_rn(t1, t2), t3), t4);
            float o  = __fsub_rn(__fadd_rn(obj_sh[jl], __fmul_rn(2.0f, ki)), wlp_sh[jl]);
            obj_sh[jl] = o;
            argmin2(bv, bi, o, j0 + jl);
        }
        block_argmin<TPB>(bv, bi, rv_sh, ri_sh, tid);
        int idx = step_exchange(t, bv, bi, tid, nb);
        if (bid == 0 && tid == 0) out[t] = (float)idx;   // output dtype: float32
        __syncthreads();
        if (tid < 2 * DIMS)
            piv[tid] = (tid < DIMS) ? x[(size_t)idx * DIMS + tid]
                                    : sp[(size_t)idx * DIMS + (tid - DIMS)];
        __syncthreads();
    }
}

extern "C" void kernel_launch(void* const* d_in, const int* in_sizes, int n_in,
                              void* d_out, int out_size) {
    // Classify inputs by element count; within each size class keep slot order.
    long maxsz = 0;
    for (int i = 0; i < n_in; i++) if ((long)in_sizes[i] > maxsz) maxsz = (long)in_sizes[i];
    long nsz = maxsz;
    for (int i = 0; i < n_in; i++) {
        long s = (long)in_sizes[i];
        if (s > 2 && s < nsz) nsz = s;
    }
    int N = (int)nsz;
    const float *x = nullptr, *sp = nullptr, *logp = nullptr, *lap = nullptr;
    const unsigned *s0 = nullptr, *s1 = nullptr;
    for (int i = 0; i < n_in; i++) {
        long s = (long)in_sizes[i];
        if (s == maxsz && s > 2) {
            if (!x) x = (const float*)d_in[i];
            else if (!sp) sp = (const float*)d_in[i];
        } else if (s == nsz && s > 2 && s != maxsz) {
            if (!logp) logp = (const float*)d_in[i];
            else if (!lap) lap = (const float*)d_in[i];
        } else if (s <= 2) {
            if (!s0) s0 = (const unsigned*)d_in[i];
            else if (!s1) s1 = (const unsigned*)d_in[i];
        }
    }
    if (!logp) { logp = x; lap = sp; }

    float* out = (float*)d_out;   // harness __output__ dtype: float32
    int m = out_size;
    if (m > MSLOTS) m = MSLOTS;

    int dev = 0;
    cudaGetDevice(&dev);
    int sms = 148;
    cudaDeviceGetAttribute(&sms, cudaDevAttrMultiProcessorCount, dev);
    int nb = sms;                          // exactly 1 block/SM (co-resident)
    int per = (N + nb - 1) / nb;           // points per block
    if (per > PERMAX) {                    // safety: more points/block than SMEM allows
        per = PERMAX;
        nb = (N + per - 1) / per;          // (should not happen on GB300: 148+ SMs)
    }

    k_setup<<<1, 1>>>(s0, s1);
    k_transpose<<<(N + 255) / 256, 256>>>((const float4*)x, (const float4*)sp, N, per);
    k_stein_pers<<<nb, TPB>>>(x, logp, sp, lap, out, nb, N, m, per);
}

// round 13
// speedup vs baseline: 1.4257x; 1.4257x over previous
#include <cuda_runtime.h>
#include <cstdint>
#include <math.h>
#include <math_constants.h>

#define DIMS 32
#define NCAP 500000
#define TPB  512
#define MSLOTS 1024
#define PERMAX 4096
#define RESID_COLS 12   // float4-columns 0..11 default policy (~96MB L2-resident), 12..15 streamed

// ---- static device scratch (no allocations allowed) ----
// 16 float4 columns: col k holds {x_k, s_k, x_{k+16}, s_{k+16}} for all points
__device__ float4 g_xs4[(size_t)16 * NCAP];
__device__ unsigned long long g_amin[MSLOTS];
__device__ unsigned g_cnt[MSLOTS];
__device__ volatile unsigned g_flag[MSLOTS];
__device__ unsigned long long g_res[MSLOTS];
__device__ float g_ell2v;

__device__ __forceinline__ unsigned f2ord(float f) {
    unsigned b = __float_as_uint(f);
    return (b & 0x80000000u) ? ~b : (b | 0x80000000u);
}

__global__ void k_setup(const unsigned* s0, const unsigned* s1) {
    int i = blockIdx.x * blockDim.x + threadIdx.x;
    if (i < MSLOTS) {
        g_amin[i] = 0xFFFFFFFFFFFFFFFFull;
        g_cnt[i] = 0u;
        g_flag[i] = 0u;
        g_res[i] = 0ull;
    }
    if (i == 0) {
        float ell = 1.0f;
        unsigned u0 = s0 ? s0[0] : 0u;
        unsigned u1 = s1 ? s1[0] : 0u;
        unsigned e0 = (u0 >> 23) & 0xffu;
        unsigned e1 = (u1 >> 23) & 0xffu;
        if (e0 >= 64u && e0 <= 191u)      ell = __uint_as_float(u0);
        else if (e1 >= 64u && e1 <= 191u) ell = __uint_as_float(u1);
        float e2 = __fmul_rn(ell, ell);
        if (!(e2 > 1e-20f) || !(e2 < 1e20f)) e2 = 1.0f;
        g_ell2v = e2;
    }
}

// x,s row-major [N][32] -> 16 float4 columns {x_k, s_k, x_{k+16}, s_{k+16}}
__global__ void __launch_bounds__(256) k_transpose(const float* __restrict__ x,
                                                   const float* __restrict__ sp,
                                                   int n) {
    int j = blockIdx.x * blockDim.x + threadIdx.x;
    if (j >= n) return;
    const float* xr = x  + (size_t)j * DIMS;
    const float* sr = sp + (size_t)j * DIMS;
    float xv[DIMS], sv[DIMS];
#pragma unroll
    for (int i = 0; i < DIMS / 4; i++) {
        float4 a = ((const float4*)xr)[i];
        float4 b = ((const float4*)sr)[i];
        xv[4*i] = a.x; xv[4*i+1] = a.y; xv[4*i+2] = a.z; xv[4*i+3] = a.w;
        sv[4*i] = b.x; sv[4*i+1] = b.y; sv[4*i+2] = b.z; sv[4*i+3] = b.w;
    }
#pragma unroll
    for (int k = 0; k < 16; k++)
        g_xs4[(size_t)k * n + j] = make_float4(xv[k], sv[k], xv[k + 16], sv[k + 16]);
}

__device__ __forceinline__ void argmin2(float& v, int& i, float v2, int i2) {
    if (v2 < v || (v2 == v && i2 < i)) { v = v2; i = i2; }
}

template <int NT>
__device__ __forceinline__ void block_argmin(float& v, int& i, float* rv, int* ri, int tid) {
#pragma unroll
    for (int off = 16; off > 0; off >>= 1) {
        float v2 = __shfl_down_sync(0xffffffffu, v, off);
        int   i2 = __shfl_down_sync(0xffffffffu, i, off);
        argmin2(v, i, v2, i2);
    }
    if ((tid & 31) == 0) { rv[tid >> 5] = v; ri[tid >> 5] = i; }
    __syncthreads();
    if (tid < 32) {
        const int nw = NT >> 5;
        float vv = (tid < nw) ? rv[tid] : CUDART_INF_F;
        int   ii = (tid < nw) ? ri[tid] : 0x7fffffff;
#pragma unroll
        for (int off = 16; off > 0; off >>= 1) {
            float v2 = __shfl_down_sync(0xffffffffu, vv, off);
            int   i2 = __shfl_down_sync(0xffffffffu, ii, off);
            argmin2(vv, ii, v2, i2);
        }
        if (tid == 0) { rv[0] = vv; ri[0] = ii; }
    }
    __syncthreads();
    v = rv[0]; i = ri[0];
}

// XLA tree over 32 (levels 2..4 applied to level-1-folded 8 partials)
__device__ __forceinline__ float tree8(float* q) {
#pragma unroll
    for (int k = 0; k < 4; k++) q[k] = __fadd_rn(q[k], q[k + 4]);
    q[0] = __fadd_rn(q[0], q[2]); q[1] = __fadd_rn(q[1], q[3]);
    return __fadd_rn(q[0], q[1]);
}
__device__ __forceinline__ float tree16(float* p) {
#pragma unroll
    for (int k = 0; k < 8; k++) p[k] = __fadd_rn(p[k], p[k + 8]);
    return tree8(p);
}

// Exchange: 1 atomicMin + 1 arrival atomic per block; last arriver publishes;
// others poll a plain volatile flag (parallel L2 reads, no atomic storm).
__device__ __forceinline__ int step_exchange(int t, float bv, int bi, int tid, int nb) {
    __shared__ unsigned long long key_sh;
    if (tid == 0) {
        unsigned long long key = ((unsigned long long)f2ord(bv) << 32) | (unsigned)bi;
        atomicMin(&g_amin[t], key);
        __threadfence();
        unsigned prev = atomicAdd(&g_cnt[t], 1u);
        if (prev == (unsigned)nb - 1u) {
            unsigned long long r = atomicAdd(&g_amin[t], 0ull);
            g_res[t] = r;
            __threadfence();
            g_flag[t] = 1u;
        } else {
            long spins = 0;
            while (g_flag[t] == 0u) {
                __nanosleep(64);
                if (++spins > 4000000L) break;
            }
        }
        __threadfence();
        key_sh = atomicAdd(&g_res[t], 0ull);   // atomic read, coherent with writer
    }
    __syncthreads();
    return (int)(unsigned)(key_sh & 0xffffffffull);
}

// ---- persistent kernel ----
__global__ void __launch_bounds__(TPB) k_stein_pers(
    const float* __restrict__ x, const float* __restrict__ logp,
    const float* __restrict__ sp, const float* __restrict__ lap,
    float* __restrict__ out, int nb, int n, int m, int per) {
    const int tid = threadIdx.x;
    const int bid = blockIdx.x;
    float ell2 = g_ell2v;
    if (!(ell2 > 1e-20f) || !(ell2 < 1e20f)) ell2 = 1.0f;
    const float e4 = __fmul_rn(ell2, ell2);
    const float w = __fdiv_rn(1.0f, (float)m);
    const float dterm = __fdiv_rn((float)DIMS, ell2);

    __shared__ float obj_sh[PERMAX];
    __shared__ float wlp_sh[PERMAX];
    __shared__ float piv[2 * DIMS];
    __shared__ float rv_sh[TPB / 32];
    __shared__ int   ri_sh[TPB / 32];

    const int j0  = bid * per;
    const int cnt = min(n - j0, per);

    // ---- step 0 ----
    {
        float bv = CUDART_INF_F; int bi = 0x7fffffff;
        const float4* s4 = (const float4*)sp;
        for (int jl = tid; jl < cnt; jl += TPB) {
            int j = j0 + jl;
            float sv[DIMS];
            const float4* row = s4 + (size_t)j * (DIMS / 4);
#pragma unroll
            for (int i = 0; i < DIMS / 4; i++) {
                float4 v = row[i];
                sv[4*i] = v.x; sv[4*i+1] = v.y; sv[4*i+2] = v.z; sv[4*i+3] = v.w;
            }
            float p[16];
#pragma unroll
            for (int k = 0; k < 16; k++)
                p[k] = __fadd_rn(__fmul_rn(sv[k], sv[k]), __fmul_rn(sv[k+16], sv[k+16]));
            float s2 = tree16(p);
            float wl = __fmul_rn(w, logp[j]);
            wlp_sh[jl] = wl;
            float o = __fsub_rn(__fadd_rn(__fadd_rn(dterm, s2), lap[j]), wl);
            obj_sh[jl] = o;
            argmin2(bv, bi, o, j);
        }
        block_argmin<TPB>(bv, bi, rv_sh, ri_sh, tid);
        int idx = step_exchange(0, bv, bi, tid, nb);
        if (bid == 0 && tid == 0) out[0] = (float)idx;
        if (tid < 2 * DIMS)
            piv[tid] = (tid < DIMS) ? x[(size_t)idx * DIMS + tid]
                                    : sp[(size_t)idx * DIMS + (tid - DIMS)];
        __syncthreads();
    }

    // ---- steps 1..m-1 ----
    for (int t = 1; t < m; t++) {
        float bv = CUDART_INF_F; int bi = 0x7fffffff;
        for (int jl = tid; jl < cnt; jl += TPB) {
            int j = j0 + jl;
            float qr[8], qa[8], qb[8], qc[8];
#pragma unroll
            for (int k = 0; k < 8; k++) {
                // col k -> dims (k, k+16); col k+8 -> dims (k+8, k+24)
                float4 A = g_xs4[(size_t)k * n + j];                       // resident policy
                float4 B = (k + 8 < RESID_COLS)
                         ? g_xs4[(size_t)(k + 8) * n + j]
                         : __ldcs(&g_xs4[(size_t)(k + 8) * n + j]);       // streamed
                float xk0 = piv[k],      sk0 = piv[DIMS + k];
                float xk1 = piv[k + 16], sk1 = piv[DIMS + k + 16];
                float xk2 = piv[k + 8],  sk2 = piv[DIMS + k + 8];
                float xk3 = piv[k + 24], sk3 = piv[DIMS + k + 24];
                float d0 = __fsub_rn(xk0, A.x);
                float d1 = __fsub_rn(xk1, A.z);
                float d2 = __fsub_rn(xk2, B.x);
                float d3 = __fsub_rn(xk3, B.z);
                // p[k] and p[k+8] of the XLA 16-tree, folded (level 1) immediately
                float pr0 = __fadd_rn(__fmul_rn(d0, d0),   __fmul_rn(d1, d1));
                float pr1 = __fadd_rn(__fmul_rn(d2, d2),   __fmul_rn(d3, d3));
                qr[k] = __fadd_rn(pr0, pr1);
                float pa0 = __fadd_rn(__fmul_rn(d0, sk0),  __fmul_rn(d1, sk1));
                float pa1 = __fadd_rn(__fmul_rn(d2, sk2),  __fmul_rn(d3, sk3));
                qa[k] = __fadd_rn(pa0, pa1);
                float pb0 = __fadd_rn(__fmul_rn(A.y, d0),  __fmul_rn(A.w, d1));
                float pb1 = __fadd_rn(__fmul_rn(B.y, d2),  __fmul_rn(B.w, d3));
                qb[k] = __fadd_rn(pb0, pb1);
                float pc0 = __fadd_rn(__fmul_rn(A.y, sk0), __fmul_rn(A.w, sk1));
                float pc1 = __fadd_rn(__fmul_rn(B.y, sk2), __fmul_rn(B.w, sk3));
                qc[k] = __fadd_rn(pc0, pc1);
            }
            float r2   = tree8(qr);
            float a    = tree8(qa);
            float b    = tree8(qb);
            float sdot = tree8(qc);

            float q    = __fadd_rn(1.0f, __fdiv_rn(r2, ell2));
            float g    = powf(q, -1.5f);
            float p25  = powf(q, -2.5f);
            float rq   = rsqrtf(q);
            float cross = __fdiv_rn(__fsub_rn(a, b), ell2);
            float t1 = __fmul_rn(dterm, g);
            float t2 = __fmul_rn(__fdiv_rn(__fmul_rn(3.0f, r2), e4), p25);
            float t3 = __fmul_rn(cross, g);
            float t4 = __fmul_rn(sdot, rq);
            float ki = __fadd_rn(__fadd_rn(__fsub_rn(t1, t2), t3), t4);
            float o  = __fsub_rn(__fadd_rn(obj_sh[jl], __fmul_rn(2.0f, ki)), wlp_sh[jl]);
            obj_sh[jl] = o;
            argmin2(bv, bi, o, j);
        }
        block_argmin<TPB>(bv, bi, rv_sh, ri_sh, tid);
        int idx = step_exchange(t, bv, bi, tid, nb);
        if (bid == 0 && tid == 0) out[t] = (float)idx;
        __syncthreads();
        if (tid < 2 * DIMS)
            piv[tid] = (tid < DIMS) ? x[(size_t)idx * DIMS + tid]
                                    : sp[(size_t)idx * DIMS + (tid - DIMS)];
        __syncthreads();
    }
}

extern "C" void kernel_launch(void* const* d_in, const int* in_sizes, int n_in,
                              void* d_out, int out_size) {
    long maxsz = 0;
    for (int i = 0; i < n_in; i++) if ((long)in_sizes[i] > maxsz) maxsz = (long)in_sizes[i];
    long nsz = maxsz;
    for (int i = 0; i < n_in; i++) {
        long s = (long)in_sizes[i];
        if (s > 2 && s < nsz) nsz = s;
    }
    int N = (int)nsz;
    const float *x = nullptr, *sp = nullptr, *logp = nullptr, *lap = nullptr;
    const unsigned *s0 = nullptr, *s1 = nullptr;
    for (int i = 0; i < n_in; i++) {
        long s = (long)in_sizes[i];
        if (s == maxsz && s > 2) {
            if (!x) x = (const float*)d_in[i];
            else if (!sp) sp = (const float*)d_in[i];
        } else if (s == nsz && s > 2 && s != maxsz) {
            if (!logp) logp = (const float*)d_in[i];
            else if (!lap) lap = (const float*)d_in[i];
        } else if (s <= 2) {
            if (!s0) s0 = (const unsigned*)d_in[i];
            else if (!s1) s1 = (const unsigned*)d_in[i];
        }
    }
    if (!logp) { logp = x; lap = sp; }

    float* out = (float*)d_out;   // harness __output__ dtype: float32
    int m = out_size;
    if (m > MSLOTS) m = MSLOTS;

    int dev = 0;
    cudaGetDevice(&dev);
    int sms = 148;
    cudaDeviceGetAttribute(&sms, cudaDevAttrMultiProcessorCount, dev);
    int nb = sms;                       // 1 block/SM
    int per = (N + nb - 1) / nb;
    if (per > PERMAX) {
        per = PERMAX;
        nb = (N + per - 1) / per;
    }

    k_setup<<<(MSLOTS + 255) / 256, 256>>>(s0, s1);
    k_transpose<<<(N + 255) / 256, 256>>>(x, sp, N);
    k_stein_pers<<<nb, TPB>>>(x, logp, sp, lap, out, nb, N, m, per);
}

// round 14
// speedup vs baseline: 1.4296x; 1.0027x over previous
#include <cuda_runtime.h>
#include <cstdint>
#include <math.h>
#include <math_constants.h>

#define DIMS 32
#define NCAP 500000
#define TPB  512
#define MSLOTS 1024
#define PERMAX 4096
#define RESID_COLS 12   // cols 0..11 (96MB) pinned via L2::evict_last; 12..15 (32MB) streamed

// ---- static device scratch (no allocations allowed) ----
// 16 float4 columns: col k holds {x_k, s_k, x_{k+16}, s_{k+16}} for all points
__device__ float4 g_xs4[(size_t)16 * NCAP];
__device__ unsigned long long g_amin[MSLOTS];
__device__ unsigned g_cnt[MSLOTS];
__device__ volatile unsigned g_flag[MSLOTS];
__device__ unsigned long long g_res[MSLOTS];
__device__ float g_ell2v;

__device__ __forceinline__ unsigned f2ord(float f) {
    unsigned b = __float_as_uint(f);
    return (b & 0x80000000u) ? ~b : (b | 0x80000000u);
}

// L2 evict_last load (keeps line resident across the 999-step re-reference)
__device__ __forceinline__ float4 ldg_keep(const float4* p, unsigned long long pol) {
    float4 v;
    asm volatile("ld.global.L2::cache_hint.v4.f32 {%0,%1,%2,%3}, [%4], %5;"
                 : "=f"(v.x), "=f"(v.y), "=f"(v.z), "=f"(v.w)
                 : "l"(p), "l"(pol));
    return v;
}

__global__ void k_setup(const unsigned* s0, const unsigned* s1) {
    int i = blockIdx.x * blockDim.x + threadIdx.x;
    if (i < MSLOTS) {
        g_amin[i] = 0xFFFFFFFFFFFFFFFFull;
        g_cnt[i] = 0u;
        g_flag[i] = 0u;
        g_res[i] = 0ull;
    }
    if (i == 0) {
        float ell = 1.0f;
        unsigned u0 = s0 ? s0[0] : 0u;
        unsigned u1 = s1 ? s1[0] : 0u;
        unsigned e0 = (u0 >> 23) & 0xffu;
        unsigned e1 = (u1 >> 23) & 0xffu;
        if (e0 >= 64u && e0 <= 191u)      ell = __uint_as_float(u0);
        else if (e1 >= 64u && e1 <= 191u) ell = __uint_as_float(u1);
        float e2 = __fmul_rn(ell, ell);
        if (!(e2 > 1e-20f) || !(e2 < 1e20f)) e2 = 1.0f;
        g_ell2v = e2;
    }
}

// x,s row-major [N][32] -> 16 float4 columns {x_k, s_k, x_{k+16}, s_{k+16}}
__global__ void __launch_bounds__(256) k_transpose(const float* __restrict__ x,
                                                   const float* __restrict__ sp,
                                                   int n) {
    int j = blockIdx.x * blockDim.x + threadIdx.x;
    if (j >= n) return;
    const float* xr = x  + (size_t)j * DIMS;
    const float* sr = sp + (size_t)j * DIMS;
    float xv[DIMS], sv[DIMS];
#pragma unroll
    for (int i = 0; i < DIMS / 4; i++) {
        float4 a = ((const float4*)xr)[i];
        float4 b = ((const float4*)sr)[i];
        xv[4*i] = a.x; xv[4*i+1] = a.y; xv[4*i+2] = a.z; xv[4*i+3] = a.w;
        sv[4*i] = b.x; sv[4*i+1] = b.y; sv[4*i+2] = b.z; sv[4*i+3] = b.w;
    }
#pragma unroll
    for (int k = 0; k < 16; k++)
        g_xs4[(size_t)k * n + j] = make_float4(xv[k], sv[k], xv[k + 16], sv[k + 16]);
}

__device__ __forceinline__ void argmin2(float& v, int& i, float v2, int i2) {
    if (v2 < v || (v2 == v && i2 < i)) { v = v2; i = i2; }
}

template <int NT>
__device__ __forceinline__ void block_argmin(float& v, int& i, float* rv, int* ri, int tid) {
#pragma unroll
    for (int off = 16; off > 0; off >>= 1) {
        float v2 = __shfl_down_sync(0xffffffffu, v, off);
        int   i2 = __shfl_down_sync(0xffffffffu, i, off);
        argmin2(v, i, v2, i2);
    }
    if ((tid & 31) == 0) { rv[tid >> 5] = v; ri[tid >> 5] = i; }
    __syncthreads();
    if (tid < 32) {
        const int nw = NT >> 5;
        float vv = (tid < nw) ? rv[tid] : CUDART_INF_F;
        int   ii = (tid < nw) ? ri[tid] : 0x7fffffff;
#pragma unroll
        for (int off = 16; off > 0; off >>= 1) {
            float v2 = __shfl_down_sync(0xffffffffu, vv, off);
            int   i2 = __shfl_down_sync(0xffffffffu, ii, off);
            argmin2(vv, ii, v2, i2);
        }
        if (tid == 0) { rv[0] = vv; ri[0] = ii; }
    }
    __syncthreads();
    v = rv[0]; i = ri[0];
}

// XLA tree over 32 (levels 2..4 applied to level-1-folded 8 partials)
__device__ __forceinline__ float tree8(float* q) {
#pragma unroll
    for (int k = 0; k < 4; k++) q[k] = __fadd_rn(q[k], q[k + 4]);
    q[0] = __fadd_rn(q[0], q[2]); q[1] = __fadd_rn(q[1], q[3]);
    return __fadd_rn(q[0], q[1]);
}
__device__ __forceinline__ float tree16(float* p) {
#pragma unroll
    for (int k = 0; k < 8; k++) p[k] = __fadd_rn(p[k], p[k + 8]);
    return tree8(p);
}

// Exchange: 1 atomicMin + 1 arrival atomic per block; last arriver publishes;
// others poll a plain volatile flag (parallel L2 reads, no atomic storm).
__device__ __forceinline__ int step_exchange(int t, float bv, int bi, int tid, int nb) {
    __shared__ unsigned long long key_sh;
    if (tid == 0) {
        unsigned long long key = ((unsigned long long)f2ord(bv) << 32) | (unsigned)bi;
        atomicMin(&g_amin[t], key);
        __threadfence();
        unsigned prev = atomicAdd(&g_cnt[t], 1u);
        if (prev == (unsigned)nb - 1u) {
            unsigned long long r = atomicAdd(&g_amin[t], 0ull);
            g_res[t] = r;
            __threadfence();
            g_flag[t] = 1u;
        } else {
            long spins = 0;
            while (g_flag[t] == 0u) {
                __nanosleep(64);
                if (++spins > 4000000L) break;
            }
        }
        __threadfence();
        key_sh = atomicAdd(&g_res[t], 0ull);   // atomic read, coherent with writer
    }
    __syncthreads();
    return (int)(unsigned)(key_sh & 0xffffffffull);
}

// ---- persistent kernel ----
__global__ void __launch_bounds__(TPB) k_stein_pers(
    const float* __restrict__ x, const float* __restrict__ logp,
    const float* __restrict__ sp, const float* __restrict__ lap,
    float* __restrict__ out, int nb, int n, int m, int per) {
    const int tid = threadIdx.x;
    const int bid = blockIdx.x;
    float ell2 = g_ell2v;
    if (!(ell2 > 1e-20f) || !(ell2 < 1e20f)) ell2 = 1.0f;
    const float e4 = __fmul_rn(ell2, ell2);
    const float w = __fdiv_rn(1.0f, (float)m);
    const float dterm = __fdiv_rn((float)DIMS, ell2);

    // L2 retention policy for the resident columns
    unsigned long long pol;
    asm volatile("createpolicy.fractional.L2::evict_last.b64 %0, 1.0;" : "=l"(pol));

    __shared__ float obj_sh[PERMAX];
    __shared__ float wlp_sh[PERMAX];
    __shared__ float piv[2 * DIMS];
    __shared__ float rv_sh[TPB / 32];
    __shared__ int   ri_sh[TPB / 32];

    const int j0  = bid * per;
    const int cnt = min(n - j0, per);

    // ---- step 0 ----
    {
        float bv = CUDART_INF_F; int bi = 0x7fffffff;
        const float4* s4 = (const float4*)sp;
        for (int jl = tid; jl < cnt; jl += TPB) {
            int j = j0 + jl;
            float sv[DIMS];
            const float4* row = s4 + (size_t)j * (DIMS / 4);
#pragma unroll
            for (int i = 0; i < DIMS / 4; i++) {
                float4 v = row[i];
                sv[4*i] = v.x; sv[4*i+1] = v.y; sv[4*i+2] = v.z; sv[4*i+3] = v.w;
            }
            float p[16];
#pragma unroll
            for (int k = 0; k < 16; k++)
                p[k] = __fadd_rn(__fmul_rn(sv[k], sv[k]), __fmul_rn(sv[k+16], sv[k+16]));
            float s2 = tree16(p);
            float wl = __fmul_rn(w, logp[j]);
            wlp_sh[jl] = wl;
            float o = __fsub_rn(__fadd_rn(__fadd_rn(dterm, s2), lap[j]), wl);
            obj_sh[jl] = o;
            argmin2(bv, bi, o, j);
        }
        block_argmin<TPB>(bv, bi, rv_sh, ri_sh, tid);
        int idx = step_exchange(0, bv, bi, tid, nb);
        if (bid == 0 && tid == 0) out[0] = (float)idx;
        if (tid < 2 * DIMS)
            piv[tid] = (tid < DIMS) ? x[(size_t)idx * DIMS + tid]
                                    : sp[(size_t)idx * DIMS + (tid - DIMS)];
        __syncthreads();
    }

    // ---- steps 1..m-1 ----
    for (int t = 1; t < m; t++) {
        float bv = CUDART_INF_F; int bi = 0x7fffffff;
        for (int jl = tid; jl < cnt; jl += TPB) {
            int j = j0 + jl;
            float qr[8], qa[8], qb[8], qc[8];
#pragma unroll
            for (int k = 0; k < 8; k++) {
                // col k -> dims (k, k+16); col k+8 -> dims (k+8, k+24)
                float4 A = ldg_keep(&g_xs4[(size_t)k * n + j], pol);       // L2-resident
                float4 B = (k + 8 < RESID_COLS)
                         ? ldg_keep(&g_xs4[(size_t)(k + 8) * n + j], pol)  // L2-resident
                         : __ldcs(&g_xs4[(size_t)(k + 8) * n + j]);        // streamed
                float xk0 = piv[k],      sk0 = piv[DIMS + k];
                float xk1 = piv[k + 16], sk1 = piv[DIMS + k + 16];
                float xk2 = piv[k + 8],  sk2 = piv[DIMS + k + 8];
                float xk3 = piv[k + 24], sk3 = piv[DIMS + k + 24];
                float d0 = __fsub_rn(xk0, A.x);
                float d1 = __fsub_rn(xk1, A.z);
                float d2 = __fsub_rn(xk2, B.x);
                float d3 = __fsub_rn(xk3, B.z);
                // p[k] and p[k+8] of the XLA 16-tree, folded (level 1) immediately
                float pr0 = __fadd_rn(__fmul_rn(d0, d0),   __fmul_rn(d1, d1));
                float pr1 = __fadd_rn(__fmul_rn(d2, d2),   __fmul_rn(d3, d3));
                qr[k] = __fadd_rn(pr0, pr1);
                float pa0 = __fadd_rn(__fmul_rn(d0, sk0),  __fmul_rn(d1, sk1));
                float pa1 = __fadd_rn(__fmul_rn(d2, sk2),  __fmul_rn(d3, sk3));
                qa[k] = __fadd_rn(pa0, pa1);
                float pb0 = __fadd_rn(__fmul_rn(A.y, d0),  __fmul_rn(A.w, d1));
                float pb1 = __fadd_rn(__fmul_rn(B.y, d2),  __fmul_rn(B.w, d3));
                qb[k] = __fadd_rn(pb0, pb1);
                float pc0 = __fadd_rn(__fmul_rn(A.y, sk0), __fmul_rn(A.w, sk1));
                float pc1 = __fadd_rn(__fmul_rn(B.y, sk2), __fmul_rn(B.w, sk3));
                qc[k] = __fadd_rn(pc0, pc1);
            }
            float r2   = tree8(qr);
            float a    = tree8(qa);
            float b    = tree8(qb);
            float sdot = tree8(qc);

            float q    = __fadd_rn(1.0f, __fdiv_rn(r2, ell2));
            float g    = powf(q, -1.5f);
            float p25  = powf(q, -2.5f);
            float rq   = rsqrtf(q);
            float cross = __fdiv_rn(__fsub_rn(a, b), ell2);
            float t1 = __fmul_rn(dterm, g);
            float t2 = __fmul_rn(__fdiv_rn(__fmul_rn(3.0f, r2), e4), p25);
            float t3 = __fmul_rn(cross, g);
            float t4 = __fmul_rn(sdot, rq);
            float ki = __fadd_rn(__fadd_rn(__fsub_rn(t1, t2), t3), t4);
            float o  = __fsub_rn(__fadd_rn(obj_sh[jl], __fmul_rn(2.0f, ki)), wlp_sh[jl]);
            obj_sh[jl] = o;
            argmin2(bv, bi, o, j);
        }
        block_argmin<TPB>(bv, bi, rv_sh, ri_sh, tid);
        int idx = step_exchange(t, bv, bi, tid, nb);
        if (bid == 0 && tid == 0) out[t] = (float)idx;
        __syncthreads();
        if (tid < 2 * DIMS)
            piv[tid] = (tid < DIMS) ? x[(size_t)idx * DIMS + tid]
                                    : sp[(size_t)idx * DIMS + (tid - DIMS)];
        __syncthreads();
    }
}

extern "C" void kernel_launch(void* const* d_in, const int* in_sizes, int n_in,
                              void* d_out, int out_size) {
    long maxsz = 0;
    for (int i = 0; i < n_in; i++) if ((long)in_sizes[i] > maxsz) maxsz = (long)in_sizes[i];
    long nsz = maxsz;
    for (int i = 0; i < n_in; i++) {
        long s = (long)in_sizes[i];
        if (s > 2 && s < nsz) nsz = s;
    }
    int N = (int)nsz;
    const float *x = nullptr, *sp = nullptr, *logp = nullptr, *lap = nullptr;
    const unsigned *s0 = nullptr, *s1 = nullptr;
    for (int i = 0; i < n_in; i++) {
        long s = (long)in_sizes[i];
        if (s == maxsz && s > 2) {
            if (!x) x = (const float*)d_in[i];
            else if (!sp) sp = (const float*)d_in[i];
        } else if (s == nsz && s > 2 && s != maxsz) {
            if (!logp) logp = (const float*)d_in[i];
            else if (!lap) lap = (const float*)d_in[i];
        } else if (s <= 2) {
            if (!s0) s0 = (const unsigned*)d_in[i];
            else if (!s1) s1 = (const unsigned*)d_in[i];
        }
    }
    if (!logp) { logp = x; lap = sp; }

    float* out = (float*)d_out;   // harness __output__ dtype: float32
    int m = out_size;
    if (m > MSLOTS) m = MSLOTS;

    int dev = 0;
    cudaGetDevice(&dev);
    int sms = 148;
    cudaDeviceGetAttribute(&sms, cudaDevAttrMultiProcessorCount, dev);
    int nb = sms;                       // 1 block/SM
    int per = (N + nb - 1) / nb;
    if (per > PERMAX) {
        per = PERMAX;
        nb = (N + per - 1) / per;
    }

    k_setup<<<(MSLOTS + 255) / 256, 256>>>(s0, s1);
    k_transpose<<<(N + 255) / 256, 256>>>(x, sp, N);
    k_stein_pers<<<nb, TPB>>>(x, logp, sp, lap, out, nb, N, m, per);
}

// round 15
// speedup vs baseline: 1.7145x; 1.1993x over previous
#include <cuda_runtime.h>
#include <cstdint>
#include <math.h>
#include <math_constants.h>

#define DIMS 32
#define NCAP 500000
#define TPB  512
#define MSLOTS 1024
#define PERMAX 4096

// ---- static device scratch (no allocations allowed) ----
// 16 float4 columns: col k holds {x_k, s_k, x_{k+16}, s_{k+16}} for all points
__device__ float4 g_xs4[(size_t)16 * NCAP];
__device__ unsigned long long g_amin[MSLOTS];
__device__ unsigned g_cnt[MSLOTS];
__device__ volatile unsigned g_flag[MSLOTS];
__device__ unsigned long long g_res[MSLOTS];
__device__ float g_ell2v;

__device__ __forceinline__ unsigned f2ord(float f) {
    unsigned b = __float_as_uint(f);
    return (b & 0x80000000u) ? ~b : (b | 0x80000000u);
}

__global__ void k_setup(const unsigned* s0, const unsigned* s1) {
    int i = blockIdx.x * blockDim.x + threadIdx.x;
    if (i < MSLOTS) {
        g_amin[i] = 0xFFFFFFFFFFFFFFFFull;
        g_cnt[i] = 0u;
        g_flag[i] = 0u;
        g_res[i] = 0ull;
    }
    if (i == 0) {
        float ell = 1.0f;
        unsigned u0 = s0 ? s0[0] : 0u;
        unsigned u1 = s1 ? s1[0] : 0u;
        unsigned e0 = (u0 >> 23) & 0xffu;
        unsigned e1 = (u1 >> 23) & 0xffu;
        if (e0 >= 64u && e0 <= 191u)      ell = __uint_as_float(u0);
        else if (e1 >= 64u && e1 <= 191u) ell = __uint_as_float(u1);
        float e2 = __fmul_rn(ell, ell);
        if (!(e2 > 1e-20f) || !(e2 < 1e20f)) e2 = 1.0f;
        g_ell2v = e2;
    }
}

// x,s row-major [N][32] -> 16 float4 columns {x_k, s_k, x_{k+16}, s_{k+16}}
__global__ void __launch_bounds__(256) k_transpose(const float* __restrict__ x,
                                                   const float* __restrict__ sp,
                                                   int n) {
    int j = blockIdx.x * blockDim.x + threadIdx.x;
    if (j >= n) return;
    const float* xr = x  + (size_t)j * DIMS;
    const float* sr = sp + (size_t)j * DIMS;
    float xv[DIMS], sv[DIMS];
#pragma unroll
    for (int i = 0; i < DIMS / 4; i++) {
        float4 a = ((const float4*)xr)[i];
        float4 b = ((const float4*)sr)[i];
        xv[4*i] = a.x; xv[4*i+1] = a.y; xv[4*i+2] = a.z; xv[4*i+3] = a.w;
        sv[4*i] = b.x; sv[4*i+1] = b.y; sv[4*i+2] = b.z; sv[4*i+3] = b.w;
    }
#pragma unroll
    for (int k = 0; k < 16; k++)
        g_xs4[(size_t)k * n + j] = make_float4(xv[k], sv[k], xv[k + 16], sv[k + 16]);
}

__device__ __forceinline__ void argmin2(float& v, int& i, float v2, int i2) {
    if (v2 < v || (v2 == v && i2 < i)) { v = v2; i = i2; }
}

template <int NT>
__device__ __forceinline__ void block_argmin(float& v, int& i, float* rv, int* ri, int tid) {
#pragma unroll
    for (int off = 16; off > 0; off >>= 1) {
        float v2 = __shfl_down_sync(0xffffffffu, v, off);
        int   i2 = __shfl_down_sync(0xffffffffu, i, off);
        argmin2(v, i, v2, i2);
    }
    if ((tid & 31) == 0) { rv[tid >> 5] = v; ri[tid >> 5] = i; }
    __syncthreads();
    if (tid < 32) {
        const int nw = NT >> 5;
        float vv = (tid < nw) ? rv[tid] : CUDART_INF_F;
        int   ii = (tid < nw) ? ri[tid] : 0x7fffffff;
#pragma unroll
        for (int off = 16; off > 0; off >>= 1) {
            float v2 = __shfl_down_sync(0xffffffffu, vv, off);
            int   i2 = __shfl_down_sync(0xffffffffu, ii, off);
            argmin2(vv, ii, v2, i2);
        }
        if (tid == 0) { rv[0] = vv; ri[0] = ii; }
    }
    __syncthreads();
    v = rv[0]; i = ri[0];
}

// XLA tree over 32 (levels 2..4 applied to level-1-folded 8 partials)
__device__ __forceinline__ float tree8(float* q) {
#pragma unroll
    for (int k = 0; k < 4; k++) q[k] = __fadd_rn(q[k], q[k + 4]);
    q[0] = __fadd_rn(q[0], q[2]); q[1] = __fadd_rn(q[1], q[3]);
    return __fadd_rn(q[0], q[1]);
}
__device__ __forceinline__ float tree16(float* p) {
#pragma unroll
    for (int k = 0; k < 8; k++) p[k] = __fadd_rn(p[k], p[k + 8]);
    return tree8(p);
}

// Exchange: 1 atomicMin + 1 arrival atomic per block; last arriver publishes;
// others poll a plain volatile flag (parallel L2 reads, no atomic storm).
__device__ __forceinline__ int step_exchange(int t, float bv, int bi, int tid, int nb) {
    __shared__ unsigned long long key_sh;
    if (tid == 0) {
        unsigned long long key = ((unsigned long long)f2ord(bv) << 32) | (unsigned)bi;
        atomicMin(&g_amin[t], key);
        __threadfence();
        unsigned prev = atomicAdd(&g_cnt[t], 1u);
        if (prev == (unsigned)nb - 1u) {
            unsigned long long r = atomicAdd(&g_amin[t], 0ull);
            g_res[t] = r;
            __threadfence();
            g_flag[t] = 1u;
        } else {
            long spins = 0;
            while (g_flag[t] == 0u) {
                __nanosleep(64);
                if (++spins > 4000000L) break;
            }
        }
        __threadfence();
        key_sh = atomicAdd(&g_res[t], 0ull);   // atomic read, coherent with writer
    }
    __syncthreads();
    return (int)(unsigned)(key_sh & 0xffffffffull);
}

// ---- persistent kernel ----
__global__ void __launch_bounds__(TPB) k_stein_pers(
    const float* __restrict__ x, const float* __restrict__ logp,
    const float* __restrict__ sp, const float* __restrict__ lap,
    float* __restrict__ out, int nb, int n, int m, int per) {
    const int tid = threadIdx.x;
    const int bid = blockIdx.x;
    float ell2 = g_ell2v;
    if (!(ell2 > 1e-20f) || !(ell2 < 1e20f)) ell2 = 1.0f;
    const float e4 = __fmul_rn(ell2, ell2);
    const float w = __fdiv_rn(1.0f, (float)m);
    const float dterm = __fdiv_rn((float)DIMS, ell2);

    __shared__ float obj_sh[PERMAX];
    __shared__ float wlp_sh[PERMAX];
    __shared__ float piv[2 * DIMS];
    __shared__ float rv_sh[TPB / 32];
    __shared__ int   ri_sh[TPB / 32];

    const int j0  = bid * per;
    const int cnt = min(n - j0, per);

    // ---- step 0 ----
    {
        float bv = CUDART_INF_F; int bi = 0x7fffffff;
        const float4* s4 = (const float4*)sp;
        for (int jl = tid; jl < cnt; jl += TPB) {
            int j = j0 + jl;
            float sv[DIMS];
            const float4* row = s4 + (size_t)j * (DIMS / 4);
#pragma unroll
            for (int i = 0; i < DIMS / 4; i++) {
                float4 v = row[i];
                sv[4*i] = v.x; sv[4*i+1] = v.y; sv[4*i+2] = v.z; sv[4*i+3] = v.w;
            }
            float p[16];
#pragma unroll
            for (int k = 0; k < 16; k++)
                p[k] = __fadd_rn(__fmul_rn(sv[k], sv[k]), __fmul_rn(sv[k+16], sv[k+16]));
            float s2 = tree16(p);
            float wl = __fmul_rn(w, logp[j]);
            wlp_sh[jl] = wl;
            float o = __fsub_rn(__fadd_rn(__fadd_rn(dterm, s2), lap[j]), wl);
            obj_sh[jl] = o;
            argmin2(bv, bi, o, j);
        }
        block_argmin<TPB>(bv, bi, rv_sh, ri_sh, tid);
        int idx = step_exchange(0, bv, bi, tid, nb);
        if (bid == 0 && tid == 0) out[0] = (float)idx;
        if (tid < 2 * DIMS)
            piv[tid] = (tid < DIMS) ? x[(size_t)idx * DIMS + tid]
                                    : sp[(size_t)idx * DIMS + (tid - DIMS)];
        __syncthreads();
    }

    // ---- steps 1..m-1, serpentine traversal (alternate direction per step) ----
    for (int t = 1; t < m; t++) {
        float bv = CUDART_INF_F; int bi = 0x7fffffff;
        const bool fwd = (t & 1);       // t=1 ascending, t=2 descending, ...
        int jl = fwd ? tid : (cnt - 1 - tid);
        const int stepj = fwd ? TPB : -TPB;
        for (; fwd ? (jl < cnt) : (jl >= 0); jl += stepj) {
            int j = j0 + jl;
            float qr[8], qa[8], qb[8], qc[8];
#pragma unroll
            for (int k = 0; k < 8; k++) {
                // col k -> dims (k, k+16); col k+8 -> dims (k+8, k+24)
                float4 A = g_xs4[(size_t)k * n + j];
                float4 B = g_xs4[(size_t)(k + 8) * n + j];
                float xk0 = piv[k],      sk0 = piv[DIMS + k];
                float xk1 = piv[k + 16], sk1 = piv[DIMS + k + 16];
                float xk2 = piv[k + 8],  sk2 = piv[DIMS + k + 8];
                float xk3 = piv[k + 24], sk3 = piv[DIMS + k + 24];
                float d0 = __fsub_rn(xk0, A.x);
                float d1 = __fsub_rn(xk1, A.z);
                float d2 = __fsub_rn(xk2, B.x);
                float d3 = __fsub_rn(xk3, B.z);
                float pr0 = __fadd_rn(__fmul_rn(d0, d0),   __fmul_rn(d1, d1));
                float pr1 = __fadd_rn(__fmul_rn(d2, d2),   __fmul_rn(d3, d3));
                qr[k] = __fadd_rn(pr0, pr1);
                float pa0 = __fadd_rn(__fmul_rn(d0, sk0),  __fmul_rn(d1, sk1));
                float pa1 = __fadd_rn(__fmul_rn(d2, sk2),  __fmul_rn(d3, sk3));
                qa[k] = __fadd_rn(pa0, pa1);
                float pb0 = __fadd_rn(__fmul_rn(A.y, d0),  __fmul_rn(A.w, d1));
                float pb1 = __fadd_rn(__fmul_rn(B.y, d2),  __fmul_rn(B.w, d3));
                qb[k] = __fadd_rn(pb0, pb1);
                float pc0 = __fadd_rn(__fmul_rn(A.y, sk0), __fmul_rn(A.w, sk1));
                float pc1 = __fadd_rn(__fmul_rn(B.y, sk2), __fmul_rn(B.w, sk3));
                qc[k] = __fadd_rn(pc0, pc1);
            }
            float r2   = tree8(qr);
            float a    = tree8(qa);
            float b    = tree8(qb);
            float sdot = tree8(qc);

            float q    = __fadd_rn(1.0f, __fdiv_rn(r2, ell2));
            float g    = powf(q, -1.5f);
            float p25  = powf(q, -2.5f);
            float rq   = rsqrtf(q);
            float cross = __fdiv_rn(__fsub_rn(a, b), ell2);
            float t1 = __fmul_rn(dterm, g);
            float t2 = __fmul_rn(__fdiv_rn(__fmul_rn(3.0f, r2), e4), p25);
            float t3 = __fmul_rn(cross, g);
            float t4 = __fmul_rn(sdot, rq);
            float ki = __fadd_rn(__fadd_rn(__fsub_rn(t1, t2), t3), t4);
            float o  = __fsub_rn(__fadd_rn(obj_sh[jl], __fmul_rn(2.0f, ki)), wlp_sh[jl]);
            obj_sh[jl] = o;
            argmin2(bv, bi, o, j);
        }
        block_argmin<TPB>(bv, bi, rv_sh, ri_sh, tid);
        int idx = step_exchange(t, bv, bi, tid, nb);
        if (bid == 0 && tid == 0) out[t] = (float)idx;
        __syncthreads();
        if (tid < 2 * DIMS)
            piv[tid] = (tid < DIMS) ? x[(size_t)idx * DIMS + tid]
                                    : sp[(size_t)idx * DIMS + (tid - DIMS)];
        __syncthreads();
    }
}

extern "C" void kernel_launch(void* const* d_in, const int* in_sizes, int n_in,
                              void* d_out, int out_size) {
    long maxsz = 0;
    for (int i = 0; i < n_in; i++) if ((long)in_sizes[i] > maxsz) maxsz = (long)in_sizes[i];
    long nsz = maxsz;
    for (int i = 0; i < n_in; i++) {
        long s = (long)in_sizes[i];
        if (s > 2 && s < nsz) nsz = s;
    }
    int N = (int)nsz;
    const float *x = nullptr, *sp = nullptr, *logp = nullptr, *lap = nullptr;
    const unsigned *s0 = nullptr, *s1 = nullptr;
    for (int i = 0; i < n_in; i++) {
        long s = (long)in_sizes[i];
        if (s == maxsz && s > 2) {
            if (!x) x = (const float*)d_in[i];
            else if (!sp) sp = (const float*)d_in[i];
        } else if (s == nsz && s > 2 && s != maxsz) {
            if (!logp) logp = (const float*)d_in[i];
            else if (!lap) lap = (const float*)d_in[i];
        } else if (s <= 2) {
            if (!s0) s0 = (const unsigned*)d_in[i];
            else if (!s1) s1 = (const unsigned*)d_in[i];
        }
    }
    if (!logp) { logp = x; lap = sp; }

    float* out = (float*)d_out;   // harness __output__ dtype: float32
    int m = out_size;
    if (m > MSLOTS) m = MSLOTS;

    int dev = 0;
    cudaGetDevice(&dev);
    int sms = 148;
    cudaDeviceGetAttribute(&sms, cudaDevAttrMultiProcessorCount, dev);
    int nb = sms;                       // 1 block/SM
    int per = (N + nb - 1) / nb;
    if (per > PERMAX) {
        per = PERMAX;
        nb = (N + per - 1) / per;
    }

    k_setup<<<(MSLOTS + 255) / 256, 256>>>(s0, s1);
    k_transpose<<<(N + 255) / 256, 256>>>(x, sp, N);
    k_stein_pers<<<nb, TPB>>>(x, logp, sp, lap, out, nb, N, m, per);
}

// round 16
// speedup vs baseline: 1.8333x; 1.0693x over previous
#include <cuda_runtime.h>
#include <cstdint>
#include <math.h>
#include <math_constants.h>

#define DIMS 32
#define NCAP 500000
#define TPB  512
#define MSLOTS 1024
#define PERMAX 3392           // >= ceil(500000/148)=3379
#define RES_PTS 768           // points pinned in SMEM per block (768*256B = 192KB)
#define DATA_BYTES ((size_t)RES_PTS * 16 * sizeof(float4))         // 196608
#define DYN_BYTES  (DATA_BYTES + (size_t)PERMAX * 2 * sizeof(float)) // +27136 = 223744

// ---- static device scratch (no allocations allowed) ----
// 16 float4 columns: col k holds {x_k, s_k, x_{k+16}, s_{k+16}} for all points
__device__ float4 g_xs4[(size_t)16 * NCAP];
__device__ unsigned long long g_amin[MSLOTS];
__device__ unsigned g_cnt[MSLOTS];
__device__ volatile unsigned g_flag[MSLOTS];
__device__ unsigned long long g_res[MSLOTS];
__device__ float g_ell2v;

__device__ __forceinline__ unsigned f2ord(float f) {
    unsigned b = __float_as_uint(f);
    return (b & 0x80000000u) ? ~b : (b | 0x80000000u);
}

__global__ void k_setup(const unsigned* s0, const unsigned* s1) {
    int i = blockIdx.x * blockDim.x + threadIdx.x;
    if (i < MSLOTS) {
        g_amin[i] = 0xFFFFFFFFFFFFFFFFull;
        g_cnt[i] = 0u;
        g_flag[i] = 0u;
        g_res[i] = 0ull;
    }
    if (i == 0) {
        float ell = 1.0f;
        unsigned u0 = s0 ? s0[0] : 0u;
        unsigned u1 = s1 ? s1[0] : 0u;
        unsigned e0 = (u0 >> 23) & 0xffu;
        unsigned e1 = (u1 >> 23) & 0xffu;
        if (e0 >= 64u && e0 <= 191u)      ell = __uint_as_float(u0);
        else if (e1 >= 64u && e1 <= 191u) ell = __uint_as_float(u1);
        float e2 = __fmul_rn(ell, ell);
        if (!(e2 > 1e-20f) || !(e2 < 1e20f)) e2 = 1.0f;
        g_ell2v = e2;
    }
}

// x,s row-major [N][32] -> 16 float4 columns {x_k, s_k, x_{k+16}, s_{k+16}}
__global__ void __launch_bounds__(256) k_transpose(const float* __restrict__ x,
                                                   const float* __restrict__ sp,
                                                   int n) {
    int j = blockIdx.x * blockDim.x + threadIdx.x;
    if (j >= n) return;
    const float* xr = x  + (size_t)j * DIMS;
    const float* sr = sp + (size_t)j * DIMS;
    float xv[DIMS], sv[DIMS];
#pragma unroll
    for (int i = 0; i < DIMS / 4; i++) {
        float4 a = ((const float4*)xr)[i];
        float4 b = ((const float4*)sr)[i];
        xv[4*i] = a.x; xv[4*i+1] = a.y; xv[4*i+2] = a.z; xv[4*i+3] = a.w;
        sv[4*i] = b.x; sv[4*i+1] = b.y; sv[4*i+2] = b.z; sv[4*i+3] = b.w;
    }
#pragma unroll
    for (int k = 0; k < 16; k++)
        g_xs4[(size_t)k * n + j] = make_float4(xv[k], sv[k], xv[k + 16], sv[k + 16]);
}

__device__ __forceinline__ void argmin2(float& v, int& i, float v2, int i2) {
    if (v2 < v || (v2 == v && i2 < i)) { v = v2; i = i2; }
}

template <int NT>
__device__ __forceinline__ void block_argmin(float& v, int& i, float* rv, int* ri, int tid) {
#pragma unroll
    for (int off = 16; off > 0; off >>= 1) {
        float v2 = __shfl_down_sync(0xffffffffu, v, off);
        int   i2 = __shfl_down_sync(0xffffffffu, i, off);
        argmin2(v, i, v2, i2);
    }
    if ((tid & 31) == 0) { rv[tid >> 5] = v; ri[tid >> 5] = i; }
    __syncthreads();
    if (tid < 32) {
        const int nw = NT >> 5;
        float vv = (tid < nw) ? rv[tid] : CUDART_INF_F;
        int   ii = (tid < nw) ? ri[tid] : 0x7fffffff;
#pragma unroll
        for (int off = 16; off > 0; off >>= 1) {
            float v2 = __shfl_down_sync(0xffffffffu, vv, off);
            int   i2 = __shfl_down_sync(0xffffffffu, ii, off);
            argmin2(vv, ii, v2, i2);
        }
        if (tid == 0) { rv[0] = vv; ri[0] = ii; }
    }
    __syncthreads();
    v = rv[0]; i = ri[0];
}

// XLA tree over 32 (levels 2..4 applied to level-1-folded 8 partials)
__device__ __forceinline__ float tree8(float* q) {
#pragma unroll
    for (int k = 0; k < 4; k++) q[k] = __fadd_rn(q[k], q[k + 4]);
    q[0] = __fadd_rn(q[0], q[2]); q[1] = __fadd_rn(q[1], q[3]);
    return __fadd_rn(q[0], q[1]);
}
__device__ __forceinline__ float tree16(float* p) {
#pragma unroll
    for (int k = 0; k < 8; k++) p[k] = __fadd_rn(p[k], p[k + 8]);
    return tree8(p);
}

// Exchange: 1 atomicMin + 1 arrival atomic per block; last arriver publishes;
// others poll a plain volatile flag (parallel L2 reads, no atomic storm).
__device__ __forceinline__ int step_exchange(int t, float bv, int bi, int tid, int nb,
                                             unsigned long long* key_sh) {
    if (tid == 0) {
        unsigned long long key = ((unsigned long long)f2ord(bv) << 32) | (unsigned)bi;
        atomicMin(&g_amin[t], key);
        __threadfence();
        unsigned prev = atomicAdd(&g_cnt[t], 1u);
        if (prev == (unsigned)nb - 1u) {
            unsigned long long r = atomicAdd(&g_amin[t], 0ull);
            g_res[t] = r;
            __threadfence();
            g_flag[t] = 1u;
        } else {
            long spins = 0;
            while (g_flag[t] == 0u) {
                __nanosleep(64);
                if (++spins > 4000000L) break;
            }
        }
        __threadfence();
        *key_sh = atomicAdd(&g_res[t], 0ull);   // atomic read, coherent with writer
    }
    __syncthreads();
    return (int)(unsigned)(*key_sh & 0xffffffffull);
}

// ---- persistent kernel; first RES_PTS points per block pinned in SMEM ----
__global__ void __launch_bounds__(TPB) k_stein_pers(
    const float* __restrict__ x, const float* __restrict__ logp,
    const float* __restrict__ sp, const float* __restrict__ lap,
    float* __restrict__ out, int nb, int n, int m, int per) {
    const int tid = threadIdx.x;
    const int bid = blockIdx.x;
    float ell2 = g_ell2v;
    if (!(ell2 > 1e-20f) || !(ell2 < 1e20f)) ell2 = 1.0f;
    const float e4 = __fmul_rn(ell2, ell2);
    const float w = __fdiv_rn(1.0f, (float)m);
    const float dterm = __fdiv_rn((float)DIMS, ell2);

    extern __shared__ char dyn_sh[];
    float4* dat_sh = (float4*)dyn_sh;                        // [16][RES_CNT]
    float*  obj_sh = (float*)(dyn_sh + DATA_BYTES);          // [PERMAX]
    float*  wlp_sh = obj_sh + PERMAX;                        // [PERMAX]

    __shared__ float piv[2 * DIMS];
    __shared__ float rv_sh[TPB / 32];
    __shared__ int   ri_sh[TPB / 32];
    __shared__ unsigned long long key_sh;

    const int j0  = bid * per;
    const int cnt = min(n - j0, per);
    const int rescnt = min(cnt, RES_PTS);

    // Pin first rescnt points' data in SMEM (one-time copy; exact fp32 copies)
    for (int i = tid; i < rescnt * 16; i += TPB) {
        int k  = i / rescnt;
        int jl = i - k * rescnt;
        dat_sh[k * rescnt + jl] = g_xs4[(size_t)k * n + (j0 + jl)];
    }

    // ---- step 0 ----
    {
        float bv = CUDART_INF_F; int bi = 0x7fffffff;
        const float4* s4 = (const float4*)sp;
        for (int jl = tid; jl < cnt; jl += TPB) {
            int j = j0 + jl;
            float sv[DIMS];
            const float4* row = s4 + (size_t)j * (DIMS / 4);
#pragma unroll
            for (int i = 0; i < DIMS / 4; i++) {
                float4 v = row[i];
                sv[4*i] = v.x; sv[4*i+1] = v.y; sv[4*i+2] = v.z; sv[4*i+3] = v.w;
            }
            float p[16];
#pragma unroll
            for (int k = 0; k < 16; k++)
                p[k] = __fadd_rn(__fmul_rn(sv[k], sv[k]), __fmul_rn(sv[k+16], sv[k+16]));
            float s2 = tree16(p);
            float wl = __fmul_rn(w, logp[j]);
            wlp_sh[jl] = wl;
            float o = __fsub_rn(__fadd_rn(__fadd_rn(dterm, s2), lap[j]), wl);
            obj_sh[jl] = o;
            argmin2(bv, bi, o, j);
        }
        block_argmin<TPB>(bv, bi, rv_sh, ri_sh, tid);
        int idx = step_exchange(0, bv, bi, tid, nb, &key_sh);
        if (bid == 0 && tid == 0) out[0] = (float)idx;
        if (tid < 2 * DIMS)
            piv[tid] = (tid < DIMS) ? x[(size_t)idx * DIMS + tid]
                                    : sp[(size_t)idx * DIMS + (tid - DIMS)];
        __syncthreads();
    }

    // ---- steps 1..m-1, serpentine traversal (alternate direction per step) ----
    for (int t = 1; t < m; t++) {
        float bv = CUDART_INF_F; int bi = 0x7fffffff;
        const bool fwd = (t & 1);
        int jl = fwd ? tid : (cnt - 1 - tid);
        const int stepj = fwd ? TPB : -TPB;
        for (; fwd ? (jl < cnt) : (jl >= 0); jl += stepj) {
            int j = j0 + jl;
            const bool res = (jl < rescnt);
            float qr[8], qa[8], qb[8], qc[8];
#pragma unroll
            for (int k = 0; k < 8; k++) {
                // col k -> dims (k, k+16); col k+8 -> dims (k+8, k+24)
                float4 A = res ? dat_sh[k * rescnt + jl]
                               : g_xs4[(size_t)k * n + j];
                float4 B = res ? dat_sh[(k + 8) * rescnt + jl]
                               : g_xs4[(size_t)(k + 8) * n + j];
                float xk0 = piv[k],      sk0 = piv[DIMS + k];
                float xk1 = piv[k + 16], sk1 = piv[DIMS + k + 16];
                float xk2 = piv[k + 8],  sk2 = piv[DIMS + k + 8];
                float xk3 = piv[k + 24], sk3 = piv[DIMS + k + 24];
                float d0 = __fsub_rn(xk0, A.x);
                float d1 = __fsub_rn(xk1, A.z);
                float d2 = __fsub_rn(xk2, B.x);
                float d3 = __fsub_rn(xk3, B.z);
                float pr0 = __fadd_rn(__fmul_rn(d0, d0),   __fmul_rn(d1, d1));
                float pr1 = __fadd_rn(__fmul_rn(d2, d2),   __fmul_rn(d3, d3));
                qr[k] = __fadd_rn(pr0, pr1);
                float pa0 = __fadd_rn(__fmul_rn(d0, sk0),  __fmul_rn(d1, sk1));
                float pa1 = __fadd_rn(__fmul_rn(d2, sk2),  __fmul_rn(d3, sk3));
                qa[k] = __fadd_rn(pa0, pa1);
                float pb0 = __fadd_rn(__fmul_rn(A.y, d0),  __fmul_rn(A.w, d1));
                float pb1 = __fadd_rn(__fmul_rn(B.y, d2),  __fmul_rn(B.w, d3));
                qb[k] = __fadd_rn(pb0, pb1);
                float pc0 = __fadd_rn(__fmul_rn(A.y, sk0), __fmul_rn(A.w, sk1));
                float pc1 = __fadd_rn(__fmul_rn(B.y, sk2), __fmul_rn(B.w, sk3));
                qc[k] = __fadd_rn(pc0, pc1);
            }
            float r2   = tree8(qr);
            float a    = tree8(qa);
            float b    = tree8(qb);
            float sdot = tree8(qc);

            float q    = __fadd_rn(1.0f, __fdiv_rn(r2, ell2));
            float g    = powf(q, -1.5f);
            float p25  = powf(q, -2.5f);
            float rq   = rsqrtf(q);
            float cross = __fdiv_rn(__fsub_rn(a, b), ell2);
            float t1 = __fmul_rn(dterm, g);
            float t2 = __fmul_rn(__fdiv_rn(__fmul_rn(3.0f, r2), e4), p25);
            float t3 = __fmul_rn(cross, g);
            float t4 = __fmul_rn(sdot, rq);
            float ki = __fadd_rn(__fadd_rn(__fsub_rn(t1, t2), t3), t4);
            float o  = __fsub_rn(__fadd_rn(obj_sh[jl], __fmul_rn(2.0f, ki)), wlp_sh[jl]);
            obj_sh[jl] = o;
            argmin2(bv, bi, o, j);
        }
        block_argmin<TPB>(bv, bi, rv_sh, ri_sh, tid);
        int idx = step_exchange(t, bv, bi, tid, nb, &key_sh);
        if (bid == 0 && tid == 0) out[t] = (float)idx;
        __syncthreads();
        if (tid < 2 * DIMS)
            piv[tid] = (tid < DIMS) ? x[(size_t)idx * DIMS + tid]
                                    : sp[(size_t)idx * DIMS + (tid - DIMS)];
        __syncthreads();
    }
}

extern "C" void kernel_launch(void* const* d_in, const int* in_sizes, int n_in,
                              void* d_out, int out_size) {
    long maxsz = 0;
    for (int i = 0; i < n_in; i++) if ((long)in_sizes[i] > maxsz) maxsz = (long)in_sizes[i];
    long nsz = maxsz;
    for (int i = 0; i < n_in; i++) {
        long s = (long)in_sizes[i];
        if (s > 2 && s < nsz) nsz = s;
    }
    int N = (int)nsz;
    const float *x = nullptr, *sp = nullptr, *logp = nullptr, *lap = nullptr;
    const unsigned *s0 = nullptr, *s1 = nullptr;
    for (int i = 0; i < n_in; i++) {
        long s = (long)in_sizes[i];
        if (s == maxsz && s > 2) {
            if (!x) x = (const float*)d_in[i];
            else if (!sp) sp = (const float*)d_in[i];
        } else if (s == nsz && s > 2 && s != maxsz) {
            if (!logp) logp = (const float*)d_in[i];
            else if (!lap) lap = (const float*)d_in[i];
        } else if (s <= 2) {
            if (!s0) s0 = (const unsigned*)d_in[i];
            else if (!s1) s1 = (const unsigned*)d_in[i];
        }
    }
    if (!logp) { logp = x; lap = sp; }

    float* out = (float*)d_out;   // harness __output__ dtype: float32
    int m = out_size;
    if (m > MSLOTS) m = MSLOTS;

    int dev = 0;
    cudaGetDevice(&dev);
    int sms = 148;
    cudaDeviceGetAttribute(&sms, cudaDevAttrMultiProcessorCount, dev);
    int nb = sms;                       // 1 block/SM
    int per = (N + nb - 1) / nb;
    if (per > PERMAX) {
        per = PERMAX;
        nb = (N + per - 1) / per;
    }

    cudaFuncSetAttribute(k_stein_pers, cudaFuncAttributeMaxDynamicSharedMemorySize,
                         (int)DYN_BYTES);

    k_setup<<<(MSLOTS + 255) / 256, 256>>>(s0, s1);
    k_transpose<<<(N + 255) / 256, 256>>>(x, sp, N);
    k_stein_pers<<<nb, TPB, DYN_BYTES>>>(x, logp, sp, lap, out, nb, N, m, per);
}